// round 1
// baseline (speedup 1.0000x reference)
#include <cuda_runtime.h>
#include <cuda_bf16.h>
#include <math.h>

#define BB 64
#define CC 512
#define KK 64
#define HW 4096

#define XSTR 18    // smem tile row stride in bf16 (conflict-friendly, keeps 4B alignment)
#define LSTR 132   // logits smem stride in floats

// ---- scratch (device globals; no allocation allowed) ----
__device__ __nv_bfloat16 g_wb[KK * CC];                 // bf16 conv weights
__device__ float         g_rnorm[BB * HW];              // 1/max(||x||,eps) per (b,hw)
__device__ __nv_bfloat16 g_assign[(size_t)BB * KK * HW];// soft assignment, bf16
__device__ float         g_asum_part[BB * KK * 32];     // per-(b,k) partial sums per i-tile
__device__ float         g_vpart[(size_t)4 * BB * KK * CC]; // split-K partial vlad

// ---------------- mma.sync bf16 m16n8k16 ----------------
__device__ __forceinline__ void mma16816(float* d, const unsigned* a, const unsigned* b) {
    asm volatile(
        "mma.sync.aligned.m16n8k16.row.col.f32.bf16.bf16.f32 "
        "{%0,%1,%2,%3}, {%4,%5,%6,%7}, {%8,%9}, {%0,%1,%2,%3};"
        : "+f"(d[0]), "+f"(d[1]), "+f"(d[2]), "+f"(d[3])
        : "r"(a[0]), "r"(a[1]), "r"(a[2]), "r"(a[3]), "r"(b[0]), "r"(b[1]));
}

// ---------------- K_pre: convert conv_w to bf16 ----------------
__global__ void k_pre(const float* __restrict__ w) {
    int t = blockIdx.x * 256 + threadIdx.x;
    if (t < KK * CC) g_wb[t] = __float2bfloat16(w[t]);
}

// ---------------- K2: fused norm + logits GEMM + softmax ----------------
// grid (HW/128, B), 256 threads. Block computes all 64 logits for 128 spatial cols.
__global__ __launch_bounds__(256) void k_logits(const float* __restrict__ x,
                                                const float* __restrict__ conv_b) {
    __shared__ __align__(16) __nv_bfloat16 Ws[KK * XSTR];
    __shared__ __align__(16) __nv_bfloat16 Xs[128 * XSTR];
    __shared__ float Ls[KK * LSTR];
    __shared__ float ssq[256];
    __shared__ float rnorm_s[128];
    __shared__ float bias_s[KK];
    __shared__ float asum4[KK * 4];

    const int b  = blockIdx.y;
    const int bi = blockIdx.x;
    const int i0 = bi * 128;
    const int t  = threadIdx.x;
    const int lane = t & 31, warp = t >> 5;
    const int mw = warp >> 1, nw = warp & 1;     // 4 m-tiles x 2 n-halves
    const int g = lane >> 2, tg = lane & 3;

    if (t < KK) bias_s[t] = conv_b[t];

    const float* xb = x + (size_t)b * CC * HW + i0;
    const unsigned* wb32 = reinterpret_cast<const unsigned*>(g_wb);

    const int iL = t & 127, chalf = t >> 7;

    float acc[8][4];
#pragma unroll
    for (int nt = 0; nt < 8; nt++)
#pragma unroll
        for (int q = 0; q < 4; q++) acc[nt][q] = 0.f;
    float ssq_loc = 0.f;

    for (int c0 = 0; c0 < CC; c0 += 16) {
        __syncthreads();
        // W chunk [64 k][16 c] -> Ws (as bf16 pairs)
#pragma unroll
        for (int p = 0; p < 2; p++) {
            int u = t + 256 * p;              // 0..511 uint32 elems
            int k = u >> 3, cp = u & 7;
            unsigned v = wb32[k * (CC / 2) + (c0 >> 1) + cp];
            *reinterpret_cast<unsigned*>(&Ws[k * XSTR + cp * 2]) = v;
        }
        // X chunk [16 c][128 i] -> Xs transposed [i][c]; accumulate sum(x^2) per col
#pragma unroll
        for (int j = 0; j < 8; j++) {
            int c = chalf * 8 + j;
            float v = xb[(size_t)(c0 + c) * HW + iL];
            ssq_loc += v * v;
            Xs[iL * XSTR + c] = __float2bfloat16(v);
        }
        __syncthreads();

        unsigned a[4];
        a[0] = *reinterpret_cast<unsigned*>(&Ws[(mw * 16 + g) * XSTR + tg * 2]);
        a[1] = *reinterpret_cast<unsigned*>(&Ws[(mw * 16 + g + 8) * XSTR + tg * 2]);
        a[2] = *reinterpret_cast<unsigned*>(&Ws[(mw * 16 + g) * XSTR + tg * 2 + 8]);
        a[3] = *reinterpret_cast<unsigned*>(&Ws[(mw * 16 + g + 8) * XSTR + tg * 2 + 8]);
#pragma unroll
        for (int nt = 0; nt < 8; nt++) {
            int col = nw * 64 + nt * 8 + g;
            unsigned bf[2];
            bf[0] = *reinterpret_cast<unsigned*>(&Xs[col * XSTR + tg * 2]);
            bf[1] = *reinterpret_cast<unsigned*>(&Xs[col * XSTR + tg * 2 + 8]);
            mma16816(acc[nt], a, bf);
        }
    }

    // reduce sum(x^2) -> rnorm
    ssq[t] = ssq_loc;
    __syncthreads();
    if (t < 128) {
        float s = ssq[t] + ssq[t + 128];
        float rn = 1.f / fmaxf(sqrtf(s), 1e-12f);
        rnorm_s[t] = rn;
        g_rnorm[b * HW + i0 + t] = rn;
    }
    __syncthreads();

    // epilogue: logits = dot * rnorm[i] + bias[k] -> Ls
#pragma unroll
    for (int nt = 0; nt < 8; nt++) {
        int col = nw * 64 + nt * 8 + tg * 2;
        int row = mw * 16 + g;
        float r0 = rnorm_s[col], r1 = rnorm_s[col + 1];
        Ls[row * LSTR + col]           = acc[nt][0] * r0 + bias_s[row];
        Ls[row * LSTR + col + 1]       = acc[nt][1] * r1 + bias_s[row];
        Ls[(row + 8) * LSTR + col]     = acc[nt][2] * r0 + bias_s[row + 8];
        Ls[(row + 8) * LSTR + col + 1] = acc[nt][3] * r1 + bias_s[row + 8];
    }
    __syncthreads();

    // softmax over k (64) per column; threads 0..127 own one column each
    if (t < 128) {
        float m = -1e30f;
        for (int k = 0; k < KK; k++) m = fmaxf(m, Ls[k * LSTR + t]);
        float s = 0.f;
        for (int k = 0; k < KK; k++) {
            float e = __expf(Ls[k * LSTR + t] - m);
            Ls[k * LSTR + t] = e;
            s += e;
        }
        float inv = 1.f / s;
        for (int k = 0; k < KK; k++) {
            float a = Ls[k * LSTR + t] * inv;
            g_assign[((size_t)(b * KK + k)) * HW + i0 + t] = __float2bfloat16(a);
            float ws = a;
#pragma unroll
            for (int o = 16; o > 0; o >>= 1) ws += __shfl_down_sync(0xffffffffu, ws, o);
            if (lane == 0) asum4[k * 4 + warp] = ws;
        }
    }
    __syncthreads();
    if (t < KK) {
        float s = asum4[t * 4] + asum4[t * 4 + 1] + asum4[t * 4 + 2] + asum4[t * 4 + 3];
        g_asum_part[(b * KK + t) * 32 + bi] = s;
    }
}

// ---------------- K3: vlad GEMM (split-K over i) ----------------
// grid (4 c2-tiles, 4 splits, B), 256 threads. D[64k x 128c2] partial over i-range 1024.
__global__ __launch_bounds__(256) void k_vlad(const float* __restrict__ x) {
    __shared__ __align__(16) __nv_bfloat16 As[KK * XSTR];
    __shared__ __align__(16) __nv_bfloat16 Xs[128 * XSTR];
    __shared__ float rnorm_s[8 * 128];

    const int c2b = blockIdx.x * 128;
    const int split = blockIdx.y;
    const int b = blockIdx.z;
    const int t = threadIdx.x;
    const int lane = t & 31, warp = t >> 5;
    const int mw = warp >> 1, nw = warp & 1;
    const int g = lane >> 2, tg = lane & 3;

    // preload rnorm for this c2 tile: rnorm index = 512*(i&7) + c2abs
    for (int u = t; u < 1024; u += 256) {
        int j8 = u >> 7, cl = u & 127;
        rnorm_s[u] = g_rnorm[b * HW + j8 * 512 + c2b + cl];
    }

    const float* xb = x + (size_t)b * CC * HW;  // flat [C*HW], reinterpreted [4096][512]
    const unsigned* asg32 =
        reinterpret_cast<const unsigned*>(g_assign + (size_t)b * KK * HW);

    const int iL = t & 127, ihalf = t >> 7;

    float acc[8][4];
#pragma unroll
    for (int nt = 0; nt < 8; nt++)
#pragma unroll
        for (int q = 0; q < 4; q++) acc[nt][q] = 0.f;

    const int ibase0 = split * 1024;
    for (int ib = 0; ib < 1024; ib += 16) {
        const int ibase = ibase0 + ib;
        __syncthreads();
        // A chunk: assign[64 k][16 i] (bf16 pairs from gmem)
#pragma unroll
        for (int p = 0; p < 2; p++) {
            int u = t + 256 * p;
            int k = u >> 3, ip = u & 7;
            unsigned v = asg32[k * (HW / 2) + (ibase >> 1) + ip];
            *reinterpret_cast<unsigned*>(&As[k * XSTR + ip * 2]) = v;
        }
        // XF chunk [16 i][128 c2] -> Xs transposed [c2][i], scaled by rnorm
#pragma unroll
        for (int j = 0; j < 8; j++) {
            int i = ihalf * 8 + j;
            float v = xb[(size_t)(ibase + i) * 512 + c2b + iL];
            v *= rnorm_s[(i & 7) * 128 + iL];
            Xs[iL * XSTR + i] = __float2bfloat16(v);
        }
        __syncthreads();

        unsigned a[4];
        a[0] = *reinterpret_cast<unsigned*>(&As[(mw * 16 + g) * XSTR + tg * 2]);
        a[1] = *reinterpret_cast<unsigned*>(&As[(mw * 16 + g + 8) * XSTR + tg * 2]);
        a[2] = *reinterpret_cast<unsigned*>(&As[(mw * 16 + g) * XSTR + tg * 2 + 8]);
        a[3] = *reinterpret_cast<unsigned*>(&As[(mw * 16 + g + 8) * XSTR + tg * 2 + 8]);
#pragma unroll
        for (int nt = 0; nt < 8; nt++) {
            int col = nw * 64 + nt * 8 + g;
            unsigned bf[2];
            bf[0] = *reinterpret_cast<unsigned*>(&Xs[col * XSTR + tg * 2]);
            bf[1] = *reinterpret_cast<unsigned*>(&Xs[col * XSTR + tg * 2 + 8]);
            mma16816(acc[nt], a, bf);
        }
    }

    float* vp = g_vpart + ((size_t)(split * BB + b)) * KK * CC;
#pragma unroll
    for (int nt = 0; nt < 8; nt++) {
        int col = c2b + nw * 64 + nt * 8 + tg * 2;
        int row = mw * 16 + g;
        vp[row * CC + col]           = acc[nt][0];
        vp[row * CC + col + 1]       = acc[nt][1];
        vp[(row + 8) * CC + col]     = acc[nt][2];
        vp[(row + 8) * CC + col + 1] = acc[nt][3];
    }
}

// ---------------- K4: combine splits, subtract asum*cent, intra + global norm ----
__global__ __launch_bounds__(256) void k_norm(const float* __restrict__ cent,
                                              float* __restrict__ out) {
    __shared__ float red[32];
    __shared__ float asum_sm[KK];
    __shared__ float bcast;

    const int b = blockIdx.x, t = threadIdx.x;
    const int lane = t & 31, warp = t >> 5;

    // asum[k] = deterministic sum of 32 per-tile partials
    for (int k = t; k < KK; k += 256) {
        const float* p = &g_asum_part[(b * KK + k) * 32];
        float s = 0.f;
        for (int j = 0; j < 32; j++) s += p[j];
        asum_sm[k] = s;
    }
    __syncthreads();

    float gss = 0.f;
    float* ob = out + (size_t)b * KK * CC;

    for (int k = 0; k < KK; k++) {
        const float as = asum_sm[k];
        const size_t base = ((size_t)b * KK + k) * CC;
        float v2[2];
        float ss = 0.f;
#pragma unroll
        for (int p = 0; p < 2; p++) {
            int c = t + 256 * p;
            float v = g_vpart[(size_t)0 * BB * KK * CC + base + c]
                    + g_vpart[(size_t)1 * BB * KK * CC + base + c]
                    + g_vpart[(size_t)2 * BB * KK * CC + base + c]
                    + g_vpart[(size_t)3 * BB * KK * CC + base + c];
            v -= as * cent[k * CC + c];
            v2[p] = v;
            ss += v * v;
        }
#pragma unroll
        for (int o = 16; o > 0; o >>= 1) ss += __shfl_down_sync(0xffffffffu, ss, o);
        if (lane == 0) red[warp] = ss;
        __syncthreads();
        if (warp == 0) {
            float s = (lane < 8) ? red[lane] : 0.f;
#pragma unroll
            for (int o = 4; o > 0; o >>= 1) s += __shfl_down_sync(0xffffffffu, s, o);
            if (lane == 0) bcast = 1.f / fmaxf(sqrtf(s), 1e-12f);
        }
        __syncthreads();
        const float rinv = bcast;
#pragma unroll
        for (int p = 0; p < 2; p++) {
            int c = t + 256 * p;
            float y = v2[p] * rinv;
            ob[k * CC + c] = y;
            gss += y * y;
        }
        __syncthreads();
    }

    // global L2 norm over 32768
#pragma unroll
    for (int o = 16; o > 0; o >>= 1) gss += __shfl_down_sync(0xffffffffu, gss, o);
    if (lane == 0) red[warp] = gss;
    __syncthreads();
    if (warp == 0) {
        float s = (lane < 8) ? red[lane] : 0.f;
#pragma unroll
        for (int o = 4; o > 0; o >>= 1) s += __shfl_down_sync(0xffffffffu, s, o);
        if (lane == 0) bcast = 1.f / fmaxf(sqrtf(s), 1e-12f);
    }
    __syncthreads();
    const float gr = bcast;
    for (int u = t; u < KK * CC; u += 256) ob[u] *= gr;
}

// ---------------- launch ----------------
extern "C" void kernel_launch(void* const* d_in, const int* in_sizes, int n_in,
                              void* d_out, int out_size) {
    (void)in_sizes; (void)n_in; (void)out_size;
    const float* x    = (const float*)d_in[0];
    const float* w    = (const float*)d_in[1];
    const float* bias = (const float*)d_in[2];
    const float* cent = (const float*)d_in[3];
    float* out = (float*)d_out;

    k_pre<<<128, 256>>>(w);
    k_logits<<<dim3(HW / 128, BB), 256>>>(x, bias);
    k_vlad<<<dim3(4, 4, BB), 256>>>(x);
    k_norm<<<BB, 256>>>(cent, out);
}

// round 2
// speedup vs baseline: 1.5063x; 1.5063x over previous
#include <cuda_runtime.h>
#include <cuda_bf16.h>
#include <math.h>

#define BB 64
#define CC 512
#define KK 64
#define HW 4096

#define XSTR 18    // smem tile row stride in bf16
#define LSTR 132   // logits smem stride in floats

// ---- scratch (device globals; no allocation allowed) ----
__device__ __align__(16) __nv_bfloat16 g_wb[KK * CC];
__device__ __align__(16) float         g_rnorm[BB * HW];
__device__ __align__(16) __nv_bfloat16 g_assign[(size_t)BB * KK * HW];
__device__ __align__(16) float         g_vpart[(size_t)4 * BB * KK * CC];
__device__ __align__(16) float         g_gss[BB * KK];

// ---------------- mma.sync bf16 m16n8k16 ----------------
__device__ __forceinline__ void mma16816(float* d, const unsigned* a, const unsigned* b) {
    asm volatile(
        "mma.sync.aligned.m16n8k16.row.col.f32.bf16.bf16.f32 "
        "{%0,%1,%2,%3}, {%4,%5,%6,%7}, {%8,%9}, {%0,%1,%2,%3};"
        : "+f"(d[0]), "+f"(d[1]), "+f"(d[2]), "+f"(d[3])
        : "r"(a[0]), "r"(a[1]), "r"(a[2]), "r"(a[3]), "r"(b[0]), "r"(b[1]));
}

// ---------------- K_pre: convert conv_w to bf16 ----------------
__global__ void k_pre(const float* __restrict__ w) {
    int t = blockIdx.x * 256 + threadIdx.x;
    if (t < KK * CC) g_wb[t] = __float2bfloat16(w[t]);
}

// ---------------- K2: fused norm + logits GEMM + softmax (double-buffered) ----
// grid (HW/128, B), 256 threads.
__global__ __launch_bounds__(256) void k_logits(const float* __restrict__ x,
                                                const float* __restrict__ conv_b) {
    // overlay region: mainloop buffers (13824 B) / Ls (33792 B)
    __shared__ __align__(16) char smA[KK * LSTR * 4];
    __shared__ float ssq[256];
    __shared__ float rnorm_s[128];
    __shared__ float bias_s[KK];

    const int b  = blockIdx.y;
    const int i0 = blockIdx.x * 128;
    const int t  = threadIdx.x;
    const int lane = t & 31, warp = t >> 5;
    const int mw = warp >> 1, nw = warp & 1;
    const int g = lane >> 2, tg = lane & 3;

    if (t < KK) bias_s[t] = conv_b[t];

    const float* xb = x + (size_t)b * CC * HW + i0;
    const unsigned* wb32 = reinterpret_cast<const unsigned*>(g_wb);
    const int iL = t & 127, chalf = t >> 7;

    // smem buffer pointers: Ws0 @0, Ws1 @2304, Xs0 @4608, Xs1 @9216
    float* Ls = reinterpret_cast<float*>(smA);

    float acc[8][4];
#pragma unroll
    for (int nt = 0; nt < 8; nt++)
#pragma unroll
        for (int q = 0; q < 4; q++) acc[nt][q] = 0.f;
    float ssq_loc = 0.f;

    const int wk = t >> 3, wc = t & 7;            // weight-load coords (2 per thread)

    float xr[8];
    unsigned wr[2];
    // prologue: load + store chunk 0
#pragma unroll
    for (int j = 0; j < 8; j++) xr[j] = xb[(size_t)(chalf * 8 + j) * HW + iL];
    wr[0] = wb32[wk * (CC / 2) + wc];
    wr[1] = wb32[(wk + 32) * (CC / 2) + wc];
    {
        __nv_bfloat16* Ws = reinterpret_cast<__nv_bfloat16*>(smA);
        __nv_bfloat16* Xs = reinterpret_cast<__nv_bfloat16*>(smA + 4608);
        *reinterpret_cast<unsigned*>(&Ws[wk * XSTR + wc * 2]) = wr[0];
        *reinterpret_cast<unsigned*>(&Ws[(wk + 32) * XSTR + wc * 2]) = wr[1];
#pragma unroll
        for (int j = 0; j < 8; j++) {
            ssq_loc += xr[j] * xr[j];
            Xs[iL * XSTR + chalf * 8 + j] = __float2bfloat16(xr[j]);
        }
    }
    __syncthreads();

    for (int it = 0; it < 32; it++) {
        const int c1 = (it + 1) * 16;
        if (it < 31) {
#pragma unroll
            for (int j = 0; j < 8; j++)
                xr[j] = xb[(size_t)(c1 + chalf * 8 + j) * HW + iL];
            wr[0] = wb32[wk * (CC / 2) + (c1 >> 1) + wc];
            wr[1] = wb32[(wk + 32) * (CC / 2) + (c1 >> 1) + wc];
        }

        const int s = it & 1;
        __nv_bfloat16* Ws = reinterpret_cast<__nv_bfloat16*>(smA + s * 2304);
        __nv_bfloat16* Xs = reinterpret_cast<__nv_bfloat16*>(smA + 4608 + s * 4608);

        unsigned a[4];
        a[0] = *reinterpret_cast<unsigned*>(&Ws[(mw * 16 + g) * XSTR + tg * 2]);
        a[1] = *reinterpret_cast<unsigned*>(&Ws[(mw * 16 + g + 8) * XSTR + tg * 2]);
        a[2] = *reinterpret_cast<unsigned*>(&Ws[(mw * 16 + g) * XSTR + tg * 2 + 8]);
        a[3] = *reinterpret_cast<unsigned*>(&Ws[(mw * 16 + g + 8) * XSTR + tg * 2 + 8]);
#pragma unroll
        for (int nt = 0; nt < 8; nt++) {
            int col = nw * 64 + nt * 8 + g;
            unsigned bf[2];
            bf[0] = *reinterpret_cast<unsigned*>(&Xs[col * XSTR + tg * 2]);
            bf[1] = *reinterpret_cast<unsigned*>(&Xs[col * XSTR + tg * 2 + 8]);
            mma16816(acc[nt], a, bf);
        }

        if (it < 31) {
            const int sn = s ^ 1;
            __nv_bfloat16* Wn = reinterpret_cast<__nv_bfloat16*>(smA + sn * 2304);
            __nv_bfloat16* Xn = reinterpret_cast<__nv_bfloat16*>(smA + 4608 + sn * 4608);
            *reinterpret_cast<unsigned*>(&Wn[wk * XSTR + wc * 2]) = wr[0];
            *reinterpret_cast<unsigned*>(&Wn[(wk + 32) * XSTR + wc * 2]) = wr[1];
#pragma unroll
            for (int j = 0; j < 8; j++) {
                ssq_loc += xr[j] * xr[j];
                Xn[iL * XSTR + chalf * 8 + j] = __float2bfloat16(xr[j]);
            }
        }
        __syncthreads();
    }

    // reduce sum(x^2) -> rnorm
    ssq[t] = ssq_loc;
    __syncthreads();
    if (t < 128) {
        float s = ssq[t] + ssq[t + 128];
        float rn = 1.f / fmaxf(sqrtf(s), 1e-12f);
        rnorm_s[t] = rn;
        g_rnorm[b * HW + i0 + t] = rn;
    }
    __syncthreads();   // buffers dead; Ls overlay becomes live

    // epilogue: logits -> Ls
#pragma unroll
    for (int nt = 0; nt < 8; nt++) {
        int col = nw * 64 + nt * 8 + tg * 2;
        int row = mw * 16 + g;
        float r0 = rnorm_s[col], r1 = rnorm_s[col + 1];
        Ls[row * LSTR + col]           = acc[nt][0] * r0 + bias_s[row];
        Ls[row * LSTR + col + 1]       = acc[nt][1] * r1 + bias_s[row];
        Ls[(row + 8) * LSTR + col]     = acc[nt][2] * r0 + bias_s[row + 8];
        Ls[(row + 8) * LSTR + col + 1] = acc[nt][3] * r1 + bias_s[row + 8];
    }
    __syncthreads();

    // softmax over k: 2 threads per column, 32 clusters each
    {
        const int col = t >> 1, kh = (t & 1) * 32;
        float m = -1e30f;
#pragma unroll 8
        for (int k2 = 0; k2 < 32; k2++) m = fmaxf(m, Ls[(kh + k2) * LSTR + col]);
        m = fmaxf(m, __shfl_xor_sync(0xffffffffu, m, 1));
        float s = 0.f;
#pragma unroll 8
        for (int k2 = 0; k2 < 32; k2++) {
            float e = __expf(Ls[(kh + k2) * LSTR + col] - m);
            Ls[(kh + k2) * LSTR + col] = e;
            s += e;
        }
        s += __shfl_xor_sync(0xffffffffu, s, 1);
        float inv = 1.f / s;
#pragma unroll 8
        for (int k2 = 0; k2 < 32; k2++) {
            float a = Ls[(kh + k2) * LSTR + col] * inv;
            g_assign[((size_t)(b * KK + kh + k2)) * HW + i0 + col] = __float2bfloat16(a);
        }
    }
}

// ---------------- K3: vlad GEMM (split-K over i, double-buffered) ----------------
// grid (4 c2-tiles, 4 splits, B), 256 threads.
__global__ __launch_bounds__(256) void k_vlad(const float* __restrict__ x) {
    __shared__ __align__(16) char smB[2 * 2304 + 2 * 4608];
    __shared__ float rnorm_s[8 * 128];

    const int c2b = blockIdx.x * 128;
    const int split = blockIdx.y;
    const int b = blockIdx.z;
    const int t = threadIdx.x;
    const int lane = t & 31, warp = t >> 5;
    const int mw = warp >> 1, nw = warp & 1;
    const int g = lane >> 2, tg = lane & 3;

    for (int u = t; u < 1024; u += 256) {
        int j8 = u >> 7, cl = u & 127;
        rnorm_s[u] = g_rnorm[b * HW + j8 * 512 + c2b + cl];
    }

    const float* xb = x + (size_t)b * CC * HW;
    const unsigned* asg32 =
        reinterpret_cast<const unsigned*>(g_assign + (size_t)b * KK * HW);

    const int iL = t & 127, ihalf = t >> 7;
    const int wk = t >> 3, wc = t & 7;

    float acc[8][4];
#pragma unroll
    for (int nt = 0; nt < 8; nt++)
#pragma unroll
        for (int q = 0; q < 4; q++) acc[nt][q] = 0.f;

    const int ibase0 = split * 1024;

    float xr[8];
    unsigned wr[2];
    // prologue chunk 0
#pragma unroll
    for (int j = 0; j < 8; j++)
        xr[j] = xb[(size_t)(ibase0 + ihalf * 8 + j) * 512 + c2b + iL];
    wr[0] = asg32[wk * (HW / 2) + (ibase0 >> 1) + wc];
    wr[1] = asg32[(wk + 32) * (HW / 2) + (ibase0 >> 1) + wc];
    __syncthreads();   // rnorm_s ready
    {
        __nv_bfloat16* As = reinterpret_cast<__nv_bfloat16*>(smB);
        __nv_bfloat16* Xs = reinterpret_cast<__nv_bfloat16*>(smB + 4608);
        *reinterpret_cast<unsigned*>(&As[wk * XSTR + wc * 2]) = wr[0];
        *reinterpret_cast<unsigned*>(&As[(wk + 32) * XSTR + wc * 2]) = wr[1];
#pragma unroll
        for (int j = 0; j < 8; j++) {
            float v = xr[j] * rnorm_s[j * 128 + iL];
            Xs[iL * XSTR + ihalf * 8 + j] = __float2bfloat16(v);
        }
    }
    __syncthreads();

    for (int it = 0; it < 64; it++) {
        const int ibn = ibase0 + (it + 1) * 16;
        if (it < 63) {
#pragma unroll
            for (int j = 0; j < 8; j++)
                xr[j] = xb[(size_t)(ibn + ihalf * 8 + j) * 512 + c2b + iL];
            wr[0] = asg32[wk * (HW / 2) + (ibn >> 1) + wc];
            wr[1] = asg32[(wk + 32) * (HW / 2) + (ibn >> 1) + wc];
        }

        const int s = it & 1;
        __nv_bfloat16* As = reinterpret_cast<__nv_bfloat16*>(smB + s * 2304);
        __nv_bfloat16* Xs = reinterpret_cast<__nv_bfloat16*>(smB + 4608 + s * 4608);

        unsigned a[4];
        a[0] = *reinterpret_cast<unsigned*>(&As[(mw * 16 + g) * XSTR + tg * 2]);
        a[1] = *reinterpret_cast<unsigned*>(&As[(mw * 16 + g + 8) * XSTR + tg * 2]);
        a[2] = *reinterpret_cast<unsigned*>(&As[(mw * 16 + g) * XSTR + tg * 2 + 8]);
        a[3] = *reinterpret_cast<unsigned*>(&As[(mw * 16 + g + 8) * XSTR + tg * 2 + 8]);
#pragma unroll
        for (int nt = 0; nt < 8; nt++) {
            int col = nw * 64 + nt * 8 + g;
            unsigned bf[2];
            bf[0] = *reinterpret_cast<unsigned*>(&Xs[col * XSTR + tg * 2]);
            bf[1] = *reinterpret_cast<unsigned*>(&Xs[col * XSTR + tg * 2 + 8]);
            mma16816(acc[nt], a, bf);
        }

        if (it < 63) {
            const int sn = s ^ 1;
            __nv_bfloat16* An = reinterpret_cast<__nv_bfloat16*>(smB + sn * 2304);
            __nv_bfloat16* Xn = reinterpret_cast<__nv_bfloat16*>(smB + 4608 + sn * 4608);
            *reinterpret_cast<unsigned*>(&An[wk * XSTR + wc * 2]) = wr[0];
            *reinterpret_cast<unsigned*>(&An[(wk + 32) * XSTR + wc * 2]) = wr[1];
#pragma unroll
            for (int j = 0; j < 8; j++) {
                float v = xr[j] * rnorm_s[j * 128 + iL];
                Xn[iL * XSTR + ihalf * 8 + j] = __float2bfloat16(v);
            }
        }
        __syncthreads();
    }

    float* vp = g_vpart + ((size_t)(split * BB + b)) * KK * CC;
#pragma unroll
    for (int nt = 0; nt < 8; nt++) {
        int col = c2b + nw * 64 + nt * 8 + tg * 2;
        int row = mw * 16 + g;
        vp[row * CC + col]           = acc[nt][0];
        vp[row * CC + col + 1]       = acc[nt][1];
        vp[(row + 8) * CC + col]     = acc[nt][2];
        vp[(row + 8) * CC + col + 1] = acc[nt][3];
    }
}

// ---------------- K4a: per-(b,k) combine + intra-normalize ----------------
// grid (KK, BB), 128 threads.
__global__ __launch_bounds__(128) void k_intra(const float* __restrict__ cent,
                                               float* __restrict__ out) {
    __shared__ float red[4];
    __shared__ float bcast;

    const int k = blockIdx.x, b = blockIdx.y;
    const int t = threadIdx.x;
    const int lane = t & 31, warp = t >> 5;

    // asum[k] = sum_i assign[b,k,i]  (deterministic tree)
    const __nv_bfloat16* ar = g_assign + ((size_t)(b * KK + k)) * HW;
    float s = 0.f;
    for (int u = t; u < HW; u += 128) s += __bfloat162float(ar[u]);
#pragma unroll
    for (int o = 16; o > 0; o >>= 1) s += __shfl_down_sync(0xffffffffu, s, o);
    if (lane == 0) red[warp] = s;
    __syncthreads();
    const float as = red[0] + red[1] + red[2] + red[3];
    __syncthreads();

    const size_t base = ((size_t)(b * KK + k)) * CC;
    const float4* c4 = reinterpret_cast<const float4*>(cent + k * CC);
    float4 v4;
    {
        const float4* p0 = reinterpret_cast<const float4*>(g_vpart + base);
        const float4* p1 = reinterpret_cast<const float4*>(g_vpart + (size_t)1 * BB * KK * CC + base);
        const float4* p2 = reinterpret_cast<const float4*>(g_vpart + (size_t)2 * BB * KK * CC + base);
        const float4* p3 = reinterpret_cast<const float4*>(g_vpart + (size_t)3 * BB * KK * CC + base);
        float4 a0 = p0[t], a1 = p1[t], a2 = p2[t], a3 = p3[t];
        float4 cc = c4[t];
        v4.x = a0.x + a1.x + a2.x + a3.x - as * cc.x;
        v4.y = a0.y + a1.y + a2.y + a3.y - as * cc.y;
        v4.z = a0.z + a1.z + a2.z + a3.z - as * cc.z;
        v4.w = a0.w + a1.w + a2.w + a3.w - as * cc.w;
    }
    float ss = v4.x * v4.x + v4.y * v4.y + v4.z * v4.z + v4.w * v4.w;
#pragma unroll
    for (int o = 16; o > 0; o >>= 1) ss += __shfl_down_sync(0xffffffffu, ss, o);
    if (lane == 0) red[warp] = ss;
    __syncthreads();
    if (t == 0) {
        float tot = red[0] + red[1] + red[2] + red[3];
        float rinv = 1.f / fmaxf(sqrtf(tot), 1e-12f);
        bcast = rinv;
        g_gss[b * KK + k] = tot * rinv * rinv;
    }
    __syncthreads();
    const float rinv = bcast;
    float4 y;
    y.x = v4.x * rinv; y.y = v4.y * rinv; y.z = v4.z * rinv; y.w = v4.w * rinv;
    reinterpret_cast<float4*>(out + base)[t] = y;
}

// ---------------- K4b: global L2 normalize ----------------
// grid (BB), 256 threads.
__global__ __launch_bounds__(256) void k_gnorm(float* __restrict__ out) {
    __shared__ float red[8];
    __shared__ float bcast;
    const int b = blockIdx.x, t = threadIdx.x;
    const int lane = t & 31, warp = t >> 5;

    float s = (t < KK) ? g_gss[b * KK + t] : 0.f;
#pragma unroll
    for (int o = 16; o > 0; o >>= 1) s += __shfl_down_sync(0xffffffffu, s, o);
    if (lane == 0) red[warp] = s;
    __syncthreads();
    if (t == 0) {
        float tot = red[0] + red[1];   // only warps 0,1 held nonzero
        bcast = 1.f / fmaxf(sqrtf(tot), 1e-12f);
    }
    __syncthreads();
    const float gr = bcast;
    float4* ob = reinterpret_cast<float4*>(out + (size_t)b * KK * CC);
#pragma unroll 4
    for (int u = t; u < KK * CC / 4; u += 256) {
        float4 v = ob[u];
        v.x *= gr; v.y *= gr; v.z *= gr; v.w *= gr;
        ob[u] = v;
    }
}

// ---------------- launch ----------------
extern "C" void kernel_launch(void* const* d_in, const int* in_sizes, int n_in,
                              void* d_out, int out_size) {
    (void)in_sizes; (void)n_in; (void)out_size;
    const float* x    = (const float*)d_in[0];
    const float* w    = (const float*)d_in[1];
    const float* bias = (const float*)d_in[2];
    const float* cent = (const float*)d_in[3];
    float* out = (float*)d_out;

    k_pre<<<128, 256>>>(w);
    k_logits<<<dim3(HW / 128, BB), 256>>>(x, bias);
    k_vlad<<<dim3(4, 4, BB), 256>>>(x);
    k_intra<<<dim3(KK, BB), 128>>>(cent, out);
    k_gnorm<<<BB, 256>>>(out);
}